// round 7
// baseline (speedup 1.0000x reference)
#include <cuda_runtime.h>
#include <math.h>
#include <float.h>

#define B_ 32
#define C_ 256
#define T_ 512
#define H_ 8
#define D_ 32
#define NEG_INF_ (-1e9f)

typedef unsigned long long u64t;

// ---- packed fp32x2 helpers (Blackwell f32x2 pipe, full fp32 precision) ----
__device__ __forceinline__ u64t dup2(float x) {
    u64t r; asm("mov.b64 %0, {%1, %1};" : "=l"(r) : "f"(x)); return r;
}
__device__ __forceinline__ void fma2(u64t& d, u64t a, u64t b) {
    asm("fma.rn.f32x2 %0, %1, %2, %0;" : "+l"(d) : "l"(a), "l"(b));
}
__device__ __forceinline__ float2 unpk(u64t v) {
    float2 r; asm("mov.b64 {%0, %1}, %2;" : "=f"(r.x), "=f"(r.y) : "l"(v)); return r;
}

// ---------------- scratch (allocation-free rule: __device__ globals) ----------
__device__ float g_Qt[B_ * C_ * T_];  // [B][H][D][T]
__device__ float g_Kt[B_ * C_ * T_];  // [B][H][D][T]
__device__ float g_Vt[B_ * C_ * T_];  // [B][H][D][T]

// ============================================================================
// Kernel 1: fused QKV projection with f32x2 microkernel.
// Tile 128(t) x 64(c), 256 threads, frag 8(t) x 4(c) per thread, x3 outputs.
// All outputs stored transposed [B][H][D][T].
// ============================================================================
__global__ __launch_bounds__(256, 2)
void qkv_kernel(const float* __restrict__ seq,
                const float* __restrict__ Wq, const float* __restrict__ bq,
                const float* __restrict__ Wk, const float* __restrict__ bk,
                const float* __restrict__ Wv, const float* __restrict__ bv) {
    __shared__ float As[32][128];
    __shared__ float Bq[32][64];
    __shared__ float Bk[32][64];
    __shared__ float Bv[32][64];

    const int b  = blockIdx.z;
    const int t0 = blockIdx.x * 128;
    const int c0 = blockIdx.y * 64;
    const int tid = threadIdx.x;
    const int tx = tid & 15;          // c quad: c0 + tx*4
    const int ry = tid >> 4;          // t rows: t0 + ry*8 .. +7

    u64t aq[8][2] = {}, ak[8][2] = {}, av[8][2] = {};
    const float* seqb = seq + b * C_ * T_;

    for (int k0 = 0; k0 < C_; k0 += 32) {
        // stage A: As[k][t], float4 coalesced along t
        #pragma unroll
        for (int it = 0; it < 4; it++) {
            int idx = tid + 256 * it;          // 0..1023 float4 slots
            int kk = idx >> 5, t4 = idx & 31;
            *(float4*)&As[kk][t4 * 4] =
                *(const float4*)&seqb[(k0 + kk) * T_ + t0 + t4 * 4];
        }
        // stage W tiles: float4 along k (global), scalar-transposed into smem
        #pragma unroll
        for (int it = 0; it < 2; it++) {
            int idx = tid + 256 * it;
            int cc = idx & 63, kk4 = idx >> 6;  // kk4 0..7
            int gi = (c0 + cc) * C_ + k0 + kk4 * 4;
            float4 wq = *(const float4*)&Wq[gi];
            float4 wk = *(const float4*)&Wk[gi];
            float4 wv = *(const float4*)&Wv[gi];
            Bq[kk4*4+0][cc] = wq.x; Bq[kk4*4+1][cc] = wq.y;
            Bq[kk4*4+2][cc] = wq.z; Bq[kk4*4+3][cc] = wq.w;
            Bk[kk4*4+0][cc] = wk.x; Bk[kk4*4+1][cc] = wk.y;
            Bk[kk4*4+2][cc] = wk.z; Bk[kk4*4+3][cc] = wk.w;
            Bv[kk4*4+0][cc] = wv.x; Bv[kk4*4+1][cc] = wv.y;
            Bv[kk4*4+2][cc] = wv.z; Bv[kk4*4+3][cc] = wv.w;
        }
        __syncthreads();
        #pragma unroll
        for (int k = 0; k < 32; k++) {
            float a[8];
            *(float4*)&a[0] = *(float4*)&As[k][ry * 8];
            *(float4*)&a[4] = *(float4*)&As[k][ry * 8 + 4];
            ulonglong2 wq = *(ulonglong2*)&Bq[k][tx * 4];
            ulonglong2 wk = *(ulonglong2*)&Bk[k][tx * 4];
            ulonglong2 wv = *(ulonglong2*)&Bv[k][tx * 4];
            #pragma unroll
            for (int i = 0; i < 8; i++) {
                u64t ad = dup2(a[i]);
                fma2(aq[i][0], ad, wq.x); fma2(aq[i][1], ad, wq.y);
                fma2(ak[i][0], ad, wk.x); fma2(ak[i][1], ad, wk.y);
                fma2(av[i][0], ad, wv.x); fma2(av[i][1], ad, wv.y);
            }
        }
        __syncthreads();
    }

    // epilogue: bias + relu, all outputs transposed [d][t] (t contiguous)
    const int c  = c0 + tx * 4;           // 4 contiguous cols, same head
    const int h  = c >> 5, jj = c & 31;
    const int bh = b * H_ + h;
    float bQ[4], bK[4], bV[4];
    *(float4*)bQ = *(const float4*)&bq[c];
    *(float4*)bK = *(const float4*)&bk[c];
    *(float4*)bV = *(const float4*)&bv[c];

    #pragma unroll
    for (int j = 0; j < 4; j++) {
        float q8[8], k8[8], v8[8];
        #pragma unroll
        for (int i = 0; i < 8; i++) {
            float2 tq = unpk(aq[i][j >> 1]);
            float2 tk = unpk(ak[i][j >> 1]);
            float2 tv = unpk(av[i][j >> 1]);
            float vq = (j & 1) ? tq.y : tq.x;
            float vk = (j & 1) ? tk.y : tk.x;
            float vv = (j & 1) ? tv.y : tv.x;
            q8[i] = fmaxf(vq + bQ[j], 0.f);
            k8[i] = fmaxf(vk + bK[j], 0.f);
            v8[i] = fmaxf(vv + bV[j], 0.f);
        }
        int base = (bh * D_ + jj + j) * T_ + t0 + ry * 8;
        *(float4*)&g_Qt[base]     = *(float4*)&q8[0];
        *(float4*)&g_Qt[base + 4] = *(float4*)&q8[4];
        *(float4*)&g_Kt[base]     = *(float4*)&k8[0];
        *(float4*)&g_Kt[base + 4] = *(float4*)&k8[4];
        *(float4*)&g_Vt[base]     = *(float4*)&v8[0];
        *(float4*)&g_Vt[base + 4] = *(float4*)&v8[4];
    }
}

// ============================================================================
// Kernel 2: attention. CTA = (hb, 64-query tile), 512 threads, f32x2 math.
// Phase1: S = Q^T K with 8r x 8c f32x2 frags (q warp-broadcast).
// Phase3: O = P V with s-paired f32x2 (P and Vt both s-contiguous, no packs).
// ============================================================================
#define QTS 68
#define KTS 524
#define SST 520
#define OFF_QT 0
#define OFF_KV (OFF_QT + 32 * QTS)          // 2176
#define OFF_S  (OFF_KV + 32 * KTS)          // 18944
#define OFF_MS (OFF_S  + 64 * SST)          // 52224
#define OFF_RI (OFF_MS + 512)               // 52736
#define ATTN_WORDS (OFF_RI + 64)            // 52800
#define SMEM_ATTN (ATTN_WORDS * 4)          // 211200 B

__global__ __launch_bounds__(512, 1)
void attn_kernel(const int* __restrict__ mask, float* __restrict__ out) {
    extern __shared__ float sm[];
    float* Qt = sm + OFF_QT;    // [32][QTS]  Q^T tile: [d][q(64)]
    float* KV = sm + OFF_KV;    // [32][KTS]  K^T then V^T: [d][s(512)]
    float* Ss = sm + OFF_S;     // [64][SST]  scores/probs
    int*   Ms = (int*)(sm + OFF_MS);
    float* Ri = sm + OFF_RI;

    const int hb = blockIdx.y;           // b*H + h
    const int b = hb >> 3, h = hb & 7;
    const int qt = blockIdx.x;           // 0..7 (64 queries each)
    const int tid = threadIdx.x;

    const float* Qg = g_Qt + hb * D_ * T_;
    const float* Kg = g_Kt + hb * D_ * T_;
    const float* Vg = g_Vt + hb * D_ * T_;

    // ---- stage Q^T tile, K^T full, mask ----
    {
        int d = tid >> 4, q4 = tid & 15;
        *(float4*)&Qt[d * QTS + q4 * 4] =
            *(const float4*)&Qg[d * T_ + qt * 64 + q4 * 4];
    }
    #pragma unroll
    for (int it = 0; it < 8; it++) {
        int idx = tid + 512 * it;            // 0..4095
        int d = idx >> 7, s4 = idx & 127;
        *(float4*)&KV[d * KTS + s4 * 4] = *(const float4*)&Kg[d * T_ + s4 * 4];
    }
    Ms[tid] = mask[b * T_ + tid];
    __syncthreads();

    // ---- phase 1: S[r][s] = (q_r . k_s)*scale, key-masked ----
    {
        const int sx = tid & 63;             // cols {4sx..4sx+3, 256+4sx..+3}
        const int rq = tid >> 6;             // rows rq*8..+7
        u64t acc[8][4] = {};                 // [i][pair]: pairs c0c1,c2c3 of both halves
        #pragma unroll
        for (int k = 0; k < 32; k++) {
            float a[8];
            *(float4*)&a[0] = *(float4*)&Qt[k * QTS + rq * 8];
            *(float4*)&a[4] = *(float4*)&Qt[k * QTS + rq * 8 + 4];
            ulonglong2 k0 = *(ulonglong2*)&KV[k * KTS + sx * 4];
            ulonglong2 k1 = *(ulonglong2*)&KV[k * KTS + 256 + sx * 4];
            #pragma unroll
            for (int i = 0; i < 8; i++) {
                u64t ad = dup2(a[i]);
                fma2(acc[i][0], ad, k0.x); fma2(acc[i][1], ad, k0.y);
                fma2(acc[i][2], ad, k1.x); fma2(acc[i][3], ad, k1.y);
            }
        }
        const float scale = 0.17677669529663687f;  // 1/sqrt(32)
        int4 m0 = *(int4*)&Ms[sx * 4];
        int4 m1 = *(int4*)&Ms[256 + sx * 4];
        #pragma unroll
        for (int i = 0; i < 8; i++) {
            float2 p0 = unpk(acc[i][0]), p1 = unpk(acc[i][1]);
            float2 p2 = unpk(acc[i][2]), p3 = unpk(acc[i][3]);
            float4 s0, s1;
            s0.x = m0.x ? p0.x * scale : NEG_INF_;
            s0.y = m0.y ? p0.y * scale : NEG_INF_;
            s0.z = m0.z ? p1.x * scale : NEG_INF_;
            s0.w = m0.w ? p1.y * scale : NEG_INF_;
            s1.x = m1.x ? p2.x * scale : NEG_INF_;
            s1.y = m1.y ? p2.y * scale : NEG_INF_;
            s1.z = m1.z ? p3.x * scale : NEG_INF_;
            s1.w = m1.w ? p3.y * scale : NEG_INF_;
            *(float4*)&Ss[(rq * 8 + i) * SST + sx * 4] = s0;
            *(float4*)&Ss[(rq * 8 + i) * SST + 256 + sx * 4] = s1;
        }
    }
    __syncthreads();

    // ---- restage V^T into KV (overwrites K; Ss hazard covered by sync) ----
    #pragma unroll
    for (int it = 0; it < 8; it++) {
        int idx = tid + 512 * it;
        int d = idx >> 7, s4 = idx & 127;
        *(float4*)&KV[d * KTS + s4 * 4] = *(const float4*)&Vg[d * T_ + s4 * 4];
    }

    // ---- phase 2: softmax per row (8 lanes/row, 64 rows) ----
    {
        const int r = tid >> 3, g = tid & 7;
        float* row = Ss + r * SST;
        float m = -FLT_MAX;
        #pragma unroll 8
        for (int k = 0; k < 64; k++) m = fmaxf(m, row[g + 8 * k]);
        #pragma unroll
        for (int o = 4; o >= 1; o >>= 1)
            m = fmaxf(m, __shfl_xor_sync(0xffffffffu, m, o));
        float lsum = 0.f;
        #pragma unroll 8
        for (int k = 0; k < 64; k++) {
            float e = __expf(row[g + 8 * k] - m);
            row[g + 8 * k] = e;
            lsum += e;
        }
        #pragma unroll
        for (int o = 4; o >= 1; o >>= 1)
            lsum += __shfl_xor_sync(0xffffffffu, lsum, o);
        if (g == 0) Ri[r] = 1.f / lsum;
    }
    __syncthreads();

    // ---- phase 3: O[r][c] = sum_s P[r][s] Vt[c][s] (pairs over s) ----
    {
        const int sq = tid & 7;              // s chunks: (m*8+sq)*4
        const int cg = (tid >> 3) & 7;       // cols cg + 8*jj, jj<4
        const int rq = tid >> 6;             // rows rq*8..+7
        u64t acc[8][4] = {};                 // [i][jj], pair = (even s, odd s)
        #pragma unroll 4
        for (int m = 0; m < 16; m++) {
            int s0 = (m * 8 + sq) * 4;
            ulonglong2 pp[8];
            #pragma unroll
            for (int i = 0; i < 8; i++)
                pp[i] = *(ulonglong2*)&Ss[(rq * 8 + i) * SST + s0];
            #pragma unroll
            for (int jj = 0; jj < 4; jj++) {
                ulonglong2 vv = *(ulonglong2*)&KV[(cg + 8 * jj) * KTS + s0];
                #pragma unroll
                for (int i = 0; i < 8; i++) {
                    fma2(acc[i][jj], pp[i].x, vv.x);
                    fma2(acc[i][jj], pp[i].y, vv.y);
                }
            }
        }
        // collapse pairs, reduce across the 8 sq lanes (butterfly)
        float res[8][4];
        #pragma unroll
        for (int i = 0; i < 8; i++)
            #pragma unroll
            for (int jj = 0; jj < 4; jj++) {
                float2 t = unpk(acc[i][jj]);
                res[i][jj] = t.x + t.y;
            }
        #pragma unroll
        for (int o = 4; o >= 1; o >>= 1)
            #pragma unroll
            for (int i = 0; i < 8; i++)
                #pragma unroll
                for (int jj = 0; jj < 4; jj++)
                    res[i][jj] += __shfl_xor_sync(0xffffffffu, res[i][jj], o);
        // lane sq stores row rq*8+sq (static index via predicated unroll)
        const int r = rq * 8 + sq;
        const float rv = Ri[r];
        float* ob = out + (b * C_ + h * D_ + cg) * T_ + qt * 64 + r;
        #pragma unroll
        for (int i = 0; i < 8; i++) {
            if (sq == i) {
                #pragma unroll
                for (int jj = 0; jj < 4; jj++)
                    ob[jj * 8 * T_] = res[i][jj] * rv;
            }
        }
    }
}

// ============================================================================
// Kernel 3: masked BatchNorm, fused two-pass, one CTA per channel, 512 thr.
// ============================================================================
__global__ __launch_bounds__(512)
void bn_kernel(const int* __restrict__ mask,
               const float* __restrict__ gamma, const float* __restrict__ beta,
               float* __restrict__ out) {
    const int c = blockIdx.x;
    const int tid = threadIdx.x;

    double s1 = 0.0, s2 = 0.0;
    for (int i = tid; i < (B_ * T_) / 4; i += 512) {
        int b = i >> 7, t4 = i & 127;
        float4 v = *(const float4*)&out[(b * C_ + c) * T_ + t4 * 4];
        int4  m = *(const int4*)&mask[b * T_ + t4 * 4];
        float x0 = m.x ? v.x : 0.f, x1 = m.y ? v.y : 0.f;
        float x2 = m.z ? v.z : 0.f, x3 = m.w ? v.w : 0.f;
        s1 += (double)x0 + (double)x1 + (double)x2 + (double)x3;
        s2 += (double)x0 * x0 + (double)x1 * x1 + (double)x2 * x2 + (double)x3 * x3;
    }
    __shared__ double sh1[512], sh2[512];
    sh1[tid] = s1; sh2[tid] = s2;
    __syncthreads();
    for (int o = 256; o > 0; o >>= 1) {
        if (tid < o) { sh1[tid] += sh1[tid + o]; sh2[tid] += sh2[tid + o]; }
        __syncthreads();
    }
    __shared__ float mean_s, rstd_s;
    if (tid == 0) {
        double mean = sh1[0] / (double)(B_ * T_);
        double var  = sh2[0] / (double)(B_ * T_) - mean * mean;
        mean_s = (float)mean;
        rstd_s = (float)(1.0 / sqrt(var + 1e-5));
    }
    __syncthreads();
    const float mean = mean_s, rstd = rstd_s, ga = gamma[c], be = beta[c];
    for (int i = tid; i < (B_ * T_) / 4; i += 512) {
        int b = i >> 7, t4 = i & 127;
        float4 v = *(float4*)&out[(b * C_ + c) * T_ + t4 * 4];
        int4  m = *(const int4*)&mask[b * T_ + t4 * 4];
        float4 r;
        r.x = m.x ? ga * (v.x - mean) * rstd + be : 0.f;
        r.y = m.y ? ga * (v.y - mean) * rstd + be : 0.f;
        r.z = m.z ? ga * (v.z - mean) * rstd + be : 0.f;
        r.w = m.w ? ga * (v.w - mean) * rstd + be : 0.f;
        *(float4*)&out[(b * C_ + c) * T_ + t4 * 4] = r;
    }
}

// ============================================================================
extern "C" void kernel_launch(void* const* d_in, const int* in_sizes, int n_in,
                              void* d_out, int out_size) {
    const float* seq   = (const float*)d_in[0];
    const int*   mask  = (const int*)  d_in[1];
    const float* Wq    = (const float*)d_in[2];
    const float* bq    = (const float*)d_in[3];
    const float* Wk    = (const float*)d_in[4];
    const float* bk    = (const float*)d_in[5];
    const float* Wv    = (const float*)d_in[6];
    const float* bv    = (const float*)d_in[7];
    const float* gamma = (const float*)d_in[8];
    const float* beta  = (const float*)d_in[9];
    float* out = (float*)d_out;

    dim3 g1(T_ / 128, C_ / 64, B_);   // 4 x 4 x 32
    qkv_kernel<<<g1, 256>>>(seq, Wq, bq, Wk, bk, Wv, bv);

    cudaFuncSetAttribute(attn_kernel, cudaFuncAttributeMaxDynamicSharedMemorySize,
                         SMEM_ATTN);
    dim3 g2(T_ / 64, B_ * H_);        // 8 x 256
    attn_kernel<<<g2, 512, SMEM_ATTN>>>(mask, out);

    bn_kernel<<<C_, 512>>>(mask, gamma, beta, out);
}

// round 8
// speedup vs baseline: 1.0026x; 1.0026x over previous
#include <cuda_runtime.h>
#include <math.h>
#include <float.h>

#define B_ 32
#define C_ 256
#define T_ 512
#define H_ 8
#define D_ 32
#define NEG_INF_ (-1e9f)

typedef unsigned long long u64t;

// ---- packed fp32x2 helpers (Blackwell f32x2 pipe, full fp32 precision) ----
__device__ __forceinline__ u64t dup2(float x) {
    u64t r; asm("mov.b64 %0, {%1, %1};" : "=l"(r) : "f"(x)); return r;
}
__device__ __forceinline__ void fma2(u64t& d, u64t a, u64t b) {
    asm("fma.rn.f32x2 %0, %1, %2, %0;" : "+l"(d) : "l"(a), "l"(b));
}
__device__ __forceinline__ float2 unpk(u64t v) {
    float2 r; asm("mov.b64 {%0, %1}, %2;" : "=f"(r.x), "=f"(r.y) : "l"(v)); return r;
}

// ---------------- scratch (allocation-free rule: __device__ globals) ----------
__device__ float g_Qt[B_ * C_ * T_];  // [B][H][D][T]
__device__ float g_Kt[B_ * C_ * T_];  // [B][H][D][T]
__device__ float g_Vt[B_ * C_ * T_];  // [B][H][D][T]

// ============================================================================
// Kernel 1: fused QKV projection with f32x2 microkernel.
// Tile 128(t) x 64(c), 256 threads, frag 8(t) x 4(c) per thread, x3 outputs.
// All outputs stored transposed [B][H][D][T].
// ============================================================================
__global__ __launch_bounds__(256, 2)
void qkv_kernel(const float* __restrict__ seq,
                const float* __restrict__ Wq, const float* __restrict__ bq,
                const float* __restrict__ Wk, const float* __restrict__ bk,
                const float* __restrict__ Wv, const float* __restrict__ bv) {
    __shared__ float As[32][128];
    __shared__ float Bq[32][64];
    __shared__ float Bk[32][64];
    __shared__ float Bv[32][64];

    const int b  = blockIdx.z;
    const int t0 = blockIdx.x * 128;
    const int c0 = blockIdx.y * 64;
    const int tid = threadIdx.x;
    const int tx = tid & 15;          // c quad: c0 + tx*4
    const int ry = tid >> 4;          // t rows: t0 + ry*8 .. +7

    u64t aq[8][2] = {}, ak[8][2] = {}, av[8][2] = {};
    const float* seqb = seq + b * C_ * T_;

    for (int k0 = 0; k0 < C_; k0 += 32) {
        // stage A: As[k][t], float4 coalesced along t
        #pragma unroll
        for (int it = 0; it < 4; it++) {
            int idx = tid + 256 * it;          // 0..1023 float4 slots
            int kk = idx >> 5, t4 = idx & 31;
            *(float4*)&As[kk][t4 * 4] =
                *(const float4*)&seqb[(k0 + kk) * T_ + t0 + t4 * 4];
        }
        // stage W tiles: float4 along k (global), scalar-transposed into smem
        #pragma unroll
        for (int it = 0; it < 2; it++) {
            int idx = tid + 256 * it;
            int cc = idx & 63, kk4 = idx >> 6;  // kk4 0..7
            int gi = (c0 + cc) * C_ + k0 + kk4 * 4;
            float4 wq = *(const float4*)&Wq[gi];
            float4 wk = *(const float4*)&Wk[gi];
            float4 wv = *(const float4*)&Wv[gi];
            Bq[kk4*4+0][cc] = wq.x; Bq[kk4*4+1][cc] = wq.y;
            Bq[kk4*4+2][cc] = wq.z; Bq[kk4*4+3][cc] = wq.w;
            Bk[kk4*4+0][cc] = wk.x; Bk[kk4*4+1][cc] = wk.y;
            Bk[kk4*4+2][cc] = wk.z; Bk[kk4*4+3][cc] = wk.w;
            Bv[kk4*4+0][cc] = wv.x; Bv[kk4*4+1][cc] = wv.y;
            Bv[kk4*4+2][cc] = wv.z; Bv[kk4*4+3][cc] = wv.w;
        }
        __syncthreads();
        #pragma unroll
        for (int k = 0; k < 32; k++) {
            float a[8];
            *(float4*)&a[0] = *(float4*)&As[k][ry * 8];
            *(float4*)&a[4] = *(float4*)&As[k][ry * 8 + 4];
            ulonglong2 wq = *(ulonglong2*)&Bq[k][tx * 4];
            ulonglong2 wk = *(ulonglong2*)&Bk[k][tx * 4];
            ulonglong2 wv = *(ulonglong2*)&Bv[k][tx * 4];
            #pragma unroll
            for (int i = 0; i < 8; i++) {
                u64t ad = dup2(a[i]);
                fma2(aq[i][0], ad, wq.x); fma2(aq[i][1], ad, wq.y);
                fma2(ak[i][0], ad, wk.x); fma2(ak[i][1], ad, wk.y);
                fma2(av[i][0], ad, wv.x); fma2(av[i][1], ad, wv.y);
            }
        }
        __syncthreads();
    }

    // epilogue: bias + relu, all outputs transposed [d][t] (t contiguous)
    const int c  = c0 + tx * 4;           // 4 contiguous cols, same head
    const int h  = c >> 5, jj = c & 31;
    const int bh = b * H_ + h;
    float bQ[4], bK[4], bV[4];
    *(float4*)bQ = *(const float4*)&bq[c];
    *(float4*)bK = *(const float4*)&bk[c];
    *(float4*)bV = *(const float4*)&bv[c];

    #pragma unroll
    for (int j = 0; j < 4; j++) {
        float q8[8], k8[8], v8[8];
        #pragma unroll
        for (int i = 0; i < 8; i++) {
            float2 tq = unpk(aq[i][j >> 1]);
            float2 tk = unpk(ak[i][j >> 1]);
            float2 tv = unpk(av[i][j >> 1]);
            float vq = (j & 1) ? tq.y : tq.x;
            float vk = (j & 1) ? tk.y : tk.x;
            float vv = (j & 1) ? tv.y : tv.x;
            q8[i] = fmaxf(vq + bQ[j], 0.f);
            k8[i] = fmaxf(vk + bK[j], 0.f);
            v8[i] = fmaxf(vv + bV[j], 0.f);
        }
        int base = (bh * D_ + jj + j) * T_ + t0 + ry * 8;
        *(float4*)&g_Qt[base]     = *(float4*)&q8[0];
        *(float4*)&g_Qt[base + 4] = *(float4*)&q8[4];
        *(float4*)&g_Kt[base]     = *(float4*)&k8[0];
        *(float4*)&g_Kt[base + 4] = *(float4*)&k8[4];
        *(float4*)&g_Vt[base]     = *(float4*)&v8[0];
        *(float4*)&g_Vt[base + 4] = *(float4*)&v8[4];
    }
}

// ============================================================================
// Kernel 2: attention. CTA = (hb, 64-query tile), 512 threads, f32x2 math.
// Phase1: S = Q^T K with 8r x 8c f32x2 frags (q warp-broadcast).
// Phase3: O = P V with s-paired f32x2 (P and Vt both s-contiguous, no packs).
// ============================================================================
#define QTS 68
#define KTS 524
#define SST 520
#define OFF_QT 0
#define OFF_KV (OFF_QT + 32 * QTS)          // 2176
#define OFF_S  (OFF_KV + 32 * KTS)          // 18944
#define OFF_MS (OFF_S  + 64 * SST)          // 52224
#define OFF_RI (OFF_MS + 512)               // 52736
#define ATTN_WORDS (OFF_RI + 64)            // 52800
#define SMEM_ATTN (ATTN_WORDS * 4)          // 211200 B

__global__ __launch_bounds__(512, 1)
void attn_kernel(const int* __restrict__ mask, float* __restrict__ out) {
    extern __shared__ float sm[];
    float* Qt = sm + OFF_QT;    // [32][QTS]  Q^T tile: [d][q(64)]
    float* KV = sm + OFF_KV;    // [32][KTS]  K^T then V^T: [d][s(512)]
    float* Ss = sm + OFF_S;     // [64][SST]  scores/probs
    int*   Ms = (int*)(sm + OFF_MS);
    float* Ri = sm + OFF_RI;

    const int hb = blockIdx.y;           // b*H + h
    const int b = hb >> 3, h = hb & 7;
    const int qt = blockIdx.x;           // 0..7 (64 queries each)
    const int tid = threadIdx.x;

    const float* Qg = g_Qt + hb * D_ * T_;
    const float* Kg = g_Kt + hb * D_ * T_;
    const float* Vg = g_Vt + hb * D_ * T_;

    // ---- stage Q^T tile, K^T full, mask ----
    {
        int d = tid >> 4, q4 = tid & 15;
        *(float4*)&Qt[d * QTS + q4 * 4] =
            *(const float4*)&Qg[d * T_ + qt * 64 + q4 * 4];
    }
    #pragma unroll
    for (int it = 0; it < 8; it++) {
        int idx = tid + 512 * it;            // 0..4095
        int d = idx >> 7, s4 = idx & 127;
        *(float4*)&KV[d * KTS + s4 * 4] = *(const float4*)&Kg[d * T_ + s4 * 4];
    }
    Ms[tid] = mask[b * T_ + tid];
    __syncthreads();

    // ---- phase 1: S[r][s] = (q_r . k_s)*scale, key-masked ----
    {
        const int sx = tid & 63;             // cols {4sx..4sx+3, 256+4sx..+3}
        const int rq = tid >> 6;             // rows rq*8..+7
        u64t acc[8][4] = {};                 // [i][pair]: pairs c0c1,c2c3 of both halves
        #pragma unroll
        for (int k = 0; k < 32; k++) {
            float a[8];
            *(float4*)&a[0] = *(float4*)&Qt[k * QTS + rq * 8];
            *(float4*)&a[4] = *(float4*)&Qt[k * QTS + rq * 8 + 4];
            ulonglong2 k0 = *(ulonglong2*)&KV[k * KTS + sx * 4];
            ulonglong2 k1 = *(ulonglong2*)&KV[k * KTS + 256 + sx * 4];
            #pragma unroll
            for (int i = 0; i < 8; i++) {
                u64t ad = dup2(a[i]);
                fma2(acc[i][0], ad, k0.x); fma2(acc[i][1], ad, k0.y);
                fma2(acc[i][2], ad, k1.x); fma2(acc[i][3], ad, k1.y);
            }
        }
        const float scale = 0.17677669529663687f;  // 1/sqrt(32)
        int4 m0 = *(int4*)&Ms[sx * 4];
        int4 m1 = *(int4*)&Ms[256 + sx * 4];
        #pragma unroll
        for (int i = 0; i < 8; i++) {
            float2 p0 = unpk(acc[i][0]), p1 = unpk(acc[i][1]);
            float2 p2 = unpk(acc[i][2]), p3 = unpk(acc[i][3]);
            float4 s0, s1;
            s0.x = m0.x ? p0.x * scale : NEG_INF_;
            s0.y = m0.y ? p0.y * scale : NEG_INF_;
            s0.z = m0.z ? p1.x * scale : NEG_INF_;
            s0.w = m0.w ? p1.y * scale : NEG_INF_;
            s1.x = m1.x ? p2.x * scale : NEG_INF_;
            s1.y = m1.y ? p2.y * scale : NEG_INF_;
            s1.z = m1.z ? p3.x * scale : NEG_INF_;
            s1.w = m1.w ? p3.y * scale : NEG_INF_;
            *(float4*)&Ss[(rq * 8 + i) * SST + sx * 4] = s0;
            *(float4*)&Ss[(rq * 8 + i) * SST + 256 + sx * 4] = s1;
        }
    }
    __syncthreads();

    // ---- restage V^T into KV (overwrites K; Ss hazard covered by sync) ----
    #pragma unroll
    for (int it = 0; it < 8; it++) {
        int idx = tid + 512 * it;
        int d = idx >> 7, s4 = idx & 127;
        *(float4*)&KV[d * KTS + s4 * 4] = *(const float4*)&Vg[d * T_ + s4 * 4];
    }

    // ---- phase 2: softmax per row (8 lanes/row, 64 rows) ----
    {
        const int r = tid >> 3, g = tid & 7;
        float* row = Ss + r * SST;
        float m = -FLT_MAX;
        #pragma unroll 8
        for (int k = 0; k < 64; k++) m = fmaxf(m, row[g + 8 * k]);
        #pragma unroll
        for (int o = 4; o >= 1; o >>= 1)
            m = fmaxf(m, __shfl_xor_sync(0xffffffffu, m, o));
        float lsum = 0.f;
        #pragma unroll 8
        for (int k = 0; k < 64; k++) {
            float e = __expf(row[g + 8 * k] - m);
            row[g + 8 * k] = e;
            lsum += e;
        }
        #pragma unroll
        for (int o = 4; o >= 1; o >>= 1)
            lsum += __shfl_xor_sync(0xffffffffu, lsum, o);
        if (g == 0) Ri[r] = 1.f / lsum;
    }
    __syncthreads();

    // ---- phase 3: O[r][c] = sum_s P[r][s] Vt[c][s] (pairs over s) ----
    {
        const int sq = tid & 7;              // s chunks: (m*8+sq)*4
        const int cg = (tid >> 3) & 7;       // cols cg + 8*jj, jj<4
        const int rq = tid >> 6;             // rows rq*8..+7
        u64t acc[8][4] = {};                 // [i][jj], pair = (even s, odd s)
        #pragma unroll 4
        for (int m = 0; m < 16; m++) {
            int s0 = (m * 8 + sq) * 4;
            ulonglong2 pp[8];
            #pragma unroll
            for (int i = 0; i < 8; i++)
                pp[i] = *(ulonglong2*)&Ss[(rq * 8 + i) * SST + s0];
            #pragma unroll
            for (int jj = 0; jj < 4; jj++) {
                ulonglong2 vv = *(ulonglong2*)&KV[(cg + 8 * jj) * KTS + s0];
                #pragma unroll
                for (int i = 0; i < 8; i++) {
                    fma2(acc[i][jj], pp[i].x, vv.x);
                    fma2(acc[i][jj], pp[i].y, vv.y);
                }
            }
        }
        // collapse pairs, reduce across the 8 sq lanes (butterfly)
        float res[8][4];
        #pragma unroll
        for (int i = 0; i < 8; i++)
            #pragma unroll
            for (int jj = 0; jj < 4; jj++) {
                float2 t = unpk(acc[i][jj]);
                res[i][jj] = t.x + t.y;
            }
        #pragma unroll
        for (int o = 4; o >= 1; o >>= 1)
            #pragma unroll
            for (int i = 0; i < 8; i++)
                #pragma unroll
                for (int jj = 0; jj < 4; jj++)
                    res[i][jj] += __shfl_xor_sync(0xffffffffu, res[i][jj], o);
        // lane sq stores row rq*8+sq (static index via predicated unroll)
        const int r = rq * 8 + sq;
        const float rv = Ri[r];
        float* ob = out + (b * C_ + h * D_ + cg) * T_ + qt * 64 + r;
        #pragma unroll
        for (int i = 0; i < 8; i++) {
            if (sq == i) {
                #pragma unroll
                for (int jj = 0; jj < 4; jj++)
                    ob[jj * 8 * T_] = res[i][jj] * rv;
            }
        }
    }
}

// ============================================================================
// Kernel 3: masked BatchNorm, fused two-pass, one CTA per channel, 512 thr.
// ============================================================================
__global__ __launch_bounds__(512)
void bn_kernel(const int* __restrict__ mask,
               const float* __restrict__ gamma, const float* __restrict__ beta,
               float* __restrict__ out) {
    const int c = blockIdx.x;
    const int tid = threadIdx.x;

    double s1 = 0.0, s2 = 0.0;
    for (int i = tid; i < (B_ * T_) / 4; i += 512) {
        int b = i >> 7, t4 = i & 127;
        float4 v = *(const float4*)&out[(b * C_ + c) * T_ + t4 * 4];
        int4  m = *(const int4*)&mask[b * T_ + t4 * 4];
        float x0 = m.x ? v.x : 0.f, x1 = m.y ? v.y : 0.f;
        float x2 = m.z ? v.z : 0.f, x3 = m.w ? v.w : 0.f;
        s1 += (double)x0 + (double)x1 + (double)x2 + (double)x3;
        s2 += (double)x0 * x0 + (double)x1 * x1 + (double)x2 * x2 + (double)x3 * x3;
    }
    __shared__ double sh1[512], sh2[512];
    sh1[tid] = s1; sh2[tid] = s2;
    __syncthreads();
    for (int o = 256; o > 0; o >>= 1) {
        if (tid < o) { sh1[tid] += sh1[tid + o]; sh2[tid] += sh2[tid + o]; }
        __syncthreads();
    }
    __shared__ float mean_s, rstd_s;
    if (tid == 0) {
        double mean = sh1[0] / (double)(B_ * T_);
        double var  = sh2[0] / (double)(B_ * T_) - mean * mean;
        mean_s = (float)mean;
        rstd_s = (float)(1.0 / sqrt(var + 1e-5));
    }
    __syncthreads();
    const float mean = mean_s, rstd = rstd_s, ga = gamma[c], be = beta[c];
    for (int i = tid; i < (B_ * T_) / 4; i += 512) {
        int b = i >> 7, t4 = i & 127;
        float4 v = *(float4*)&out[(b * C_ + c) * T_ + t4 * 4];
        int4  m = *(const int4*)&mask[b * T_ + t4 * 4];
        float4 r;
        r.x = m.x ? ga * (v.x - mean) * rstd + be : 0.f;
        r.y = m.y ? ga * (v.y - mean) * rstd + be : 0.f;
        r.z = m.z ? ga * (v.z - mean) * rstd + be : 0.f;
        r.w = m.w ? ga * (v.w - mean) * rstd + be : 0.f;
        *(float4*)&out[(b * C_ + c) * T_ + t4 * 4] = r;
    }
}

// ============================================================================
extern "C" void kernel_launch(void* const* d_in, const int* in_sizes, int n_in,
                              void* d_out, int out_size) {
    const float* seq   = (const float*)d_in[0];
    const int*   mask  = (const int*)  d_in[1];
    const float* Wq    = (const float*)d_in[2];
    const float* bq    = (const float*)d_in[3];
    const float* Wk    = (const float*)d_in[4];
    const float* bk    = (const float*)d_in[5];
    const float* Wv    = (const float*)d_in[6];
    const float* bv    = (const float*)d_in[7];
    const float* gamma = (const float*)d_in[8];
    const float* beta  = (const float*)d_in[9];
    float* out = (float*)d_out;

    dim3 g1(T_ / 128, C_ / 64, B_);   // 4 x 4 x 32
    qkv_kernel<<<g1, 256>>>(seq, Wq, bq, Wk, bk, Wv, bv);

    cudaFuncSetAttribute(attn_kernel, cudaFuncAttributeMaxDynamicSharedMemorySize,
                         SMEM_ATTN);
    dim3 g2(T_ / 64, B_ * H_);        // 8 x 256
    attn_kernel<<<g2, 512, SMEM_ATTN>>>(mask, out);

    bn_kernel<<<C_, 512>>>(mask, gamma, beta, out);
}